// round 13
// baseline (speedup 1.0000x reference)
#include <cuda_runtime.h>
#include <cuda_bf16.h>
#include <cuda_fp16.h>
#include <cstdint>

#define BATCH 512
#define NH    50      // history length
#define ED    128     // embed dim
#define HD    200     // hidden dim
#define NE    50000   // num entities
#define KP    208     // K padded to 13*16 for mma
#define GX    391     // gemm grid x (ceil(NE/128))

// ---------------- device scratch (allowed: __device__ globals) ----------------
__device__ float          g_c[BATCH * NH];                 // final routing coefficients
__device__ float          g_u[(size_t)BATCH * NH * HD];    // u_hat f32 [25600][200] (20.5MB)
__device__ __nv_bfloat16  g_vb[BATCH * KP];                // v (poses) in bf16, K-padded
__device__ __nv_bfloat16  g_Wb[(size_t)NE * KP];           // mlp_w in bf16, K-padded (20.8MB)
__device__ __half         g_es[(size_t)BATCH * NE];        // exp(scores) fp16 (51.2MB)
__device__ float          g_up[BATCH];                     // uniform p value per row
__device__ float          g_inv[BATCH];                    // 1 / rowsum(exp(scores))
__device__ float          g_pval[BATCH * NH];              // p value per (row, owner-slot), -1 if dup
__device__ float          g_part[(size_t)BATCH * GX];      // per-block row partial sums

// packed f32x2 helpers (sm_103a)
#define PACK2(p, x, y)   asm("mov.b64 %0, {%1, %2};" : "=l"(p) : "f"(x), "f"(y))
#define UNPACK2(x, y, p) asm("mov.b64 {%0, %1}, %2;" : "=f"(x), "=f"(y) : "l"(p))
#define FMA2(d, a, b)    asm("fma.rn.f32x2 %0, %1, %2, %0;" : "+l"(d) : "l"(a), "l"(b))

// ---------------- K0: convert mlp_w f32 -> bf16, pad K to 208 ----------------
__global__ void k_convw(const float* __restrict__ W) {
    int e = blockIdx.x;
    int k = threadIdx.x;
    if (k < KP)
        g_Wb[(size_t)e * KP + k] =
            __float2bfloat16(k < HD ? W[(size_t)e * HD + k] : 0.f);
}

// ---------------- K1a: x = gather(emb) @ Ws^T + b, L2-normalized -> g_u -------
// Fully parallel GEMM: 25600 rows x 200 h x 128 d. 800 blocks x 256 thr.
// Tile: 32 rows x 200 h. Thread = (rg 0..3, hq 0..63; hq<50 active):
// owns 8 rows x 4 h, accumulated as f32x2 pairs (rows packed).
__global__ void __launch_bounds__(256, 3) k_x(
    const int* __restrict__ idx, const float* __restrict__ emb,
    const float* __restrict__ Wsw, const float* __restrict__ Wsb)
{
    extern __shared__ float sm[];
    float* Ws_s = sm;                  // 32 dd x 256 h-pad = 8192 w
    float* E_t  = sm + 8192;           // 128 d x 36 row-pad = 4608 w
    int*   sidx = (int*)&sm[12800];    // 32
    float* ninv = &sm[12832];          // 32
    float* red  = sm;                  // overlay on Ws_s: [32 rows][64 hq]

    const int tid = threadIdx.x;
    const int rg = tid >> 6;           // 0..3
    const int hq = tid & 63;           // 0..63 (active < 50)
    const int rbase = rg << 3;
    const bool valid = (hq < 50);

    if (tid < 32) sidx[tid] = idx[blockIdx.x * 32 + tid];
    __syncthreads();
    // gather embeddings transposed: E_t[d][row]
    for (int i = tid; i < 32 * 32; i += 256) {
        int row = i >> 5, c4 = i & 31;
        const float4 v = *(const float4*)&emb[(size_t)sidx[row] * ED + c4 * 4];
        int d0 = c4 * 4;
        E_t[(d0 + 0) * 36 + row] = v.x;
        E_t[(d0 + 1) * 36 + row] = v.y;
        E_t[(d0 + 2) * 36 + row] = v.z;
        E_t[(d0 + 3) * 36 + row] = v.w;
    }

    unsigned long long acc2[16];   // [rp 0..3][k 0..3]: (x[2rp][k], x[2rp+1][k])
#pragma unroll
    for (int i = 0; i < 16; ++i) PACK2(acc2[i], 0.f, 0.f);

    for (int c = 0; c < 4; ++c) {
        __syncthreads();   // prev chunk compute done (and E gather at c=0)
        for (int i = tid; i < 6400; i += 256) {
            int h = i >> 5, dd = i & 31;
            Ws_s[dd * 256 + h] = Wsw[h * ED + (c << 5) + dd];
        }
        __syncthreads();
#pragma unroll 8
        for (int dd = 0; dd < 32; ++dd) {
            int d = (c << 5) + dd;
            float4 w  = *(float4*)&Ws_s[dd * 256 + hq * 4];
            float4 ea = *(float4*)&E_t[d * 36 + rbase];
            float4 eb = *(float4*)&E_t[d * 36 + rbase + 4];
            unsigned long long e2[4], w2[4];
            PACK2(e2[0], ea.x, ea.y); PACK2(e2[1], ea.z, ea.w);
            PACK2(e2[2], eb.x, eb.y); PACK2(e2[3], eb.z, eb.w);
            PACK2(w2[0], w.x, w.x);   PACK2(w2[1], w.y, w.y);
            PACK2(w2[2], w.z, w.z);   PACK2(w2[3], w.w, w.w);
#pragma unroll
            for (int rp = 0; rp < 4; ++rp)
#pragma unroll
                for (int k = 0; k < 4; ++k)
                    FMA2(acc2[rp * 4 + k], e2[rp], w2[k]);
        }
    }

    // unpack + bias, per-row squared partials
    float4 bs = make_float4(0.f, 0.f, 0.f, 0.f);
    if (valid) bs = *(const float4*)&Wsb[hq * 4];
    float bsa[4] = {bs.x, bs.y, bs.z, bs.w};
    float xv[8][4];
#pragma unroll
    for (int rp = 0; rp < 4; ++rp)
#pragma unroll
        for (int k = 0; k < 4; ++k) {
            float lo, hi;
            UNPACK2(lo, hi, acc2[rp * 4 + k]);
            xv[2 * rp][k]     = lo + bsa[k];
            xv[2 * rp + 1][k] = hi + bsa[k];
        }
    __syncthreads();   // done reading Ws_s; red overlay safe
#pragma unroll
    for (int r = 0; r < 8; ++r) {
        float p = xv[r][0] * xv[r][0] + xv[r][1] * xv[r][1]
                + xv[r][2] * xv[r][2] + xv[r][3] * xv[r][3];
        red[(rbase + r) * 64 + hq] = valid ? p : 0.f;
    }
    __syncthreads();
    {   // reduce 64 hq per row: 8 lanes per row
        int row = tid >> 3, q0 = tid & 7;
        float s = 0.f;
        for (int q = q0; q < 64; q += 8) s += red[row * 64 + q];
        s += __shfl_xor_sync(0xffffffffu, s, 1);
        s += __shfl_xor_sync(0xffffffffu, s, 2);
        s += __shfl_xor_sync(0xffffffffu, s, 4);
        if (q0 == 0) ninv[row] = 1.0f / fmaxf(sqrtf(s), 1e-12f);
    }
    __syncthreads();
    if (valid) {
#pragma unroll
        for (int r = 0; r < 8; ++r) {
            float f = ninv[rbase + r];
            size_t R = (size_t)blockIdx.x * 32 + rbase + r;
            float4 o = make_float4(xv[r][0] * f, xv[r][1] * f,
                                   xv[r][2] * f, xv[r][3] * f);
            *(float4*)&g_u[R * HD + hq * 4] = o;
        }
    }
}

// ---------------- K1b: dynamic routing on smem-resident u_hat -----------------
__global__ void __launch_bounds__(256, 4) k_rout2(const int* __restrict__ times)
{
    extern __shared__ float sm[];
    float* X    = sm;            // 50 x 200 = 10000 w
    float* bvec = &sm[10016];    // 50
    float* cvec = &sm[10080];    // 50
    float* vvec = &sm[10144];    // 200
    float* red  = &sm[10368];    // 256
    const int row  = blockIdx.x;
    const int tid  = threadIdx.x;
    const int lane = tid & 31;
    const int warp = tid >> 5;

    if (tid < NH)
        bvec[tid] = 2.0f / (1.0f + (float)times[row * NH + tid]); // (W+1)/(W+t), W=1
    for (int i = tid; i < NH * HD; i += 256)
        X[i] = g_u[(size_t)row * NH * HD + i];
    __syncthreads();

    // dynamic routing: 3 iterations
    float sh = 0.f;
    for (int r = 0; r < 3; ++r) {
        if (warp == 0) {  // softmax over bvec[0..49] * 50
            float x1 = (lane < NH) ? bvec[lane] : -1e30f;
            float x2 = (lane + 32 < NH) ? bvec[lane + 32] : -1e30f;
            float m = fmaxf(x1, x2);
#pragma unroll
            for (int o = 16; o > 0; o >>= 1) m = fmaxf(m, __shfl_xor_sync(0xffffffffu, m, o));
            float e1 = (lane < NH) ? __expf(x1 - m) : 0.f;
            float e2 = (lane + 32 < NH) ? __expf(x2 - m) : 0.f;
            float s = e1 + e2;
#pragma unroll
            for (int o = 16; o > 0; o >>= 1) s += __shfl_xor_sync(0xffffffffu, s, o);
            float inv = (float)NH / s;
            if (lane < NH) cvec[lane] = e1 * inv;
            if (lane + 32 < NH) cvec[lane + 32] = e2 * inv;
        }
        __syncthreads();
        // s[h] = sum_n c[n] * u[n][h]
        sh = 0.f;
        if (tid < HD) {
#pragma unroll 5
            for (int n = 0; n < NH; ++n) sh = fmaf(cvec[n], X[n * HD + tid], sh);
        }
        red[tid] = (tid < HD) ? sh * sh : 0.f;
        __syncthreads();
        for (int s2 = 128; s2 > 0; s2 >>= 1) {
            if (tid < s2) red[tid] += red[tid + s2];
            __syncthreads();
        }
        float sq = red[0];
        float scale = sq / ((1.0f + sq) * sqrtf(sq + 1e-9f));  // squash
        if (tid < HD) vvec[tid] = scale * sh;
        __syncthreads();
        if (r < 2) {  // b[n] += u[n] . v
            for (int n = warp; n < NH; n += 8) {
                float p = 0.f;
                for (int h = lane; h < HD; h += 32) p = fmaf(X[n * HD + h], vvec[h], p);
#pragma unroll
                for (int o = 16; o > 0; o >>= 1) p += __shfl_xor_sync(0xffffffffu, p, o);
                if (lane == 0) bvec[n] += p;
            }
            __syncthreads();
        }
    }

    // outputs
    if (tid < NH) g_c[row * NH + tid] = cvec[tid];
    if (tid < KP)
        g_vb[row * KP + tid] = __float2bfloat16((tid < HD) ? vvec[tid] : 0.f);
}

// ---------------- K2: p-row prep (dedupe scatter + closed-form softmax) -------
__global__ void __launch_bounds__(64) k_pprep(const int* __restrict__ idx)
{
    __shared__ int   sid[64];
    __shared__ float sc[64];
    __shared__ float red[64];
    int row = blockIdx.x, tid = threadIdx.x;
    if (tid < NH) { sid[tid] = idx[row * NH + tid]; sc[tid] = g_c[row * NH + tid]; }
    __syncthreads();
    bool owner = false; float csum = 0.f;
    if (tid < NH) {
        int e = sid[tid]; owner = true;
        for (int k = 0; k < NH; ++k)
            if (sid[k] == e) { if (k < tid) owner = false; csum += sc[k]; }
    }
    red[tid] = (tid < NH && owner) ? csum : -1e30f;
    __syncthreads();
    for (int s = 32; s > 0; s >>= 1) { if (tid < s) red[tid] = fmaxf(red[tid], red[tid + s]); __syncthreads(); }
    float pmax = red[0];
    __syncthreads();
    red[tid] = (tid < NH && owner) ? __expf(csum - pmax) : 0.f;
    __syncthreads();
    for (int s = 32; s > 0; s >>= 1) { if (tid < s) red[tid] += red[tid + s]; __syncthreads(); }
    float s1 = red[0];
    __syncthreads();
    red[tid] = (tid < NH && owner) ? 1.f : 0.f;
    __syncthreads();
    for (int s = 32; s > 0; s >>= 1) { if (tid < s) red[tid] += red[tid + s]; __syncthreads(); }
    float dcount = red[0];
    float eneg   = __expf(-pmax);
    float denom  = s1 + ((float)NE - dcount) * eneg;
    if (tid == 0)  g_up[row] = eneg / denom;
    if (tid < NH)  g_pval[row * NH + tid] = owner ? (__expf(csum - pmax) / denom) : -1.0f;
}

// ---------------- K3: scores GEMM (bf16 mma.sync + ldmatrix, fp32 accum) ------
// block tile 128m x 128n, 8 warps (2m x 4n), warp tile 64m x 32n, K = 13x16.
// Epilogue: exp(score+bias) -> g_es (fp16), deterministic row partials -> g_part.
__global__ void __launch_bounds__(256, 2) k_gemm(const float* __restrict__ bias)
{
    extern __shared__ char smem_raw[];
    __nv_bfloat16* sA = (__nv_bfloat16*)smem_raw;             // 128 x 216 = 55296 B
    __nv_bfloat16* sB = (__nv_bfloat16*)(smem_raw + 55296);   // 128 x 216 = 55296 B
    float* s_part = (float*)(smem_raw + 110592);              // [4][128]

    const int tid  = threadIdx.x;
    const int warp = tid >> 5, lane = tid & 31;
    const int g = lane >> 2, t = lane & 3;
    const int mw = warp >> 2, nw = warp & 3;
    const int mblk = blockIdx.y * 128;
    const int eblk = blockIdx.x * 128;

    // stage A (always-valid rows) and B (guard e < NE), 26 uint4 per 208-col row
    for (int i = tid; i < 128 * 26; i += 256) {
        int r = i / 26, c8 = i % 26;
        uint4 v = *(const uint4*)&g_vb[(size_t)(mblk + r) * KP + c8 * 8];
        *(uint4*)&sA[r * 216 + c8 * 8] = v;
    }
    for (int i = tid; i < 128 * 26; i += 256) {
        int r = i / 26, c8 = i % 26;
        int e = eblk + r;
        uint4 v = make_uint4(0u, 0u, 0u, 0u);
        if (e < NE) v = *(const uint4*)&g_Wb[(size_t)e * KP + c8 * 8];
        *(uint4*)&sB[r * 216 + c8 * 8] = v;
    }
    __syncthreads();

    float acc[4][4][4];
#pragma unroll
    for (int a = 0; a < 4; a++)
#pragma unroll
        for (int b = 0; b < 4; b++)
#pragma unroll
            for (int c = 0; c < 4; c++) acc[a][b][c] = 0.f;

    // ldmatrix lane addresses (byte addrs in shared space)
    uint32_t aAd[4], bAd[2];
    {
        int arow = lane & 15, ahalf = lane >> 4;
#pragma unroll
        for (int mt = 0; mt < 4; ++mt)
            aAd[mt] = (uint32_t)__cvta_generic_to_shared(
                &sA[(mw * 64 + mt * 16 + arow) * 216 + ahalf * 8]);
        int brow  = ((lane >> 4) << 3) + (lane & 7);
        int bhalf = (lane >> 3) & 1;
#pragma unroll
        for (int p = 0; p < 2; ++p)
            bAd[p] = (uint32_t)__cvta_generic_to_shared(
                &sB[(nw * 32 + p * 16 + brow) * 216 + bhalf * 8]);
    }

#pragma unroll
    for (int kc = 0; kc < 13; ++kc) {
        const uint32_t off = kc * 32;   // 16 bf16 = 32 bytes
        uint32_t af[4][4], bf2[2][4];
#pragma unroll
        for (int mt = 0; mt < 4; ++mt)
            asm volatile("ldmatrix.sync.aligned.m8n8.x4.shared.b16 {%0,%1,%2,%3}, [%4];"
                : "=r"(af[mt][0]), "=r"(af[mt][1]), "=r"(af[mt][2]), "=r"(af[mt][3])
                : "r"(aAd[mt] + off));
#pragma unroll
        for (int p = 0; p < 2; ++p)
            asm volatile("ldmatrix.sync.aligned.m8n8.x4.shared.b16 {%0,%1,%2,%3}, [%4];"
                : "=r"(bf2[p][0]), "=r"(bf2[p][1]), "=r"(bf2[p][2]), "=r"(bf2[p][3])
                : "r"(bAd[p] + off));
#pragma unroll
        for (int mt = 0; mt < 4; ++mt)
#pragma unroll
            for (int nt = 0; nt < 4; ++nt) {
                const uint32_t b0 = bf2[nt >> 1][(nt & 1) * 2];
                const uint32_t b1 = bf2[nt >> 1][(nt & 1) * 2 + 1];
                asm volatile(
                    "mma.sync.aligned.m16n8k16.row.col.f32.bf16.bf16.f32 "
                    "{%0,%1,%2,%3}, {%4,%5,%6,%7}, {%8,%9}, {%0,%1,%2,%3};\n"
                    : "+f"(acc[mt][nt][0]), "+f"(acc[mt][nt][1]),
                      "+f"(acc[mt][nt][2]), "+f"(acc[mt][nt][3])
                    : "r"(af[mt][0]), "r"(af[mt][1]), "r"(af[mt][2]), "r"(af[mt][3]),
                      "r"(b0), "r"(b1));
            }
    }

    // epilogue: exp(score + bias) -> fp16 scratch (|score|<0.3, no max-sub needed)
    float rsum[4][2];
#pragma unroll
    for (int mt = 0; mt < 4; ++mt) { rsum[mt][0] = 0.f; rsum[mt][1] = 0.f; }
#pragma unroll
    for (int mt = 0; mt < 4; ++mt) {
        int r0 = mblk + mw * 64 + mt * 16 + g;
#pragma unroll
        for (int nt = 0; nt < 4; ++nt) {
            int e0 = eblk + nw * 32 + nt * 8 + 2 * t;
            if (e0 < NE) {
                float b0v = bias[e0], b1v = bias[e0 + 1];
                float u0 = __expf(acc[mt][nt][0] + b0v);
                float u1 = __expf(acc[mt][nt][1] + b1v);
                float l0 = __expf(acc[mt][nt][2] + b0v);
                float l1 = __expf(acc[mt][nt][3] + b1v);
                *(__half2*)&g_es[(size_t)r0 * NE + e0]       = __floats2half2_rn(u0, u1);
                *(__half2*)&g_es[(size_t)(r0 + 8) * NE + e0] = __floats2half2_rn(l0, l1);
                rsum[mt][0] += u0 + u1;
                rsum[mt][1] += l0 + l1;
            }
        }
    }
    // deterministic per-row partial sums: reduce over t lanes, then over nw warps
#pragma unroll
    for (int mt = 0; mt < 4; ++mt) {
#pragma unroll
        for (int h = 0; h < 2; ++h) {
            float s = rsum[mt][h];
            s += __shfl_xor_sync(0xffffffffu, s, 1);
            s += __shfl_xor_sync(0xffffffffu, s, 2);
            if (t == 0) s_part[nw * 128 + mw * 64 + mt * 16 + h * 8 + g] = s;
        }
    }
    __syncthreads();
    if (tid < 128) {
        float s = s_part[tid] + s_part[128 + tid] + s_part[256 + tid] + s_part[384 + tid];
        g_part[(size_t)(mblk + tid) * GX + blockIdx.x] = s;
    }
}

// ---------------- K3b: reduce per-block partials -> 1/rowsum ------------------
__global__ void __launch_bounds__(128) k_rowsum()
{
    __shared__ float red[128];
    int row = blockIdx.x, tid = threadIdx.x;
    float s = 0.f;
    for (int i = tid; i < GX; i += 128) s += g_part[(size_t)row * GX + i];
    red[tid] = s; __syncthreads();
    for (int st = 64; st > 0; st >>= 1) {
        if (tid < st) red[tid] += red[tid + st];
        __syncthreads();
    }
    if (tid == 0) g_inv[row] = 1.0f / red[0];
}

// ---------------- K4: out = log(0.5*p_uniform + 0.5*sims) ---------------------
__global__ void __launch_bounds__(256) k_final(float* __restrict__ out)
{
    size_t i = (size_t)blockIdx.x * blockDim.x + threadIdx.x;   // quad index
    int row = (int)(i / (NE / 4));
    float up  = 0.5f * g_up[row];
    float inv = 0.5f * g_inv[row];
    uint2 raw = ((const uint2*)g_es)[i];
    float2 f01 = __half22float2(*(__half2*)&raw.x);
    float2 f23 = __half22float2(*(__half2*)&raw.y);
    float4 o;
    o.x = __logf(fmaf(f01.x, inv, up));
    o.y = __logf(fmaf(f01.y, inv, up));
    o.z = __logf(fmaf(f23.x, inv, up));
    o.w = __logf(fmaf(f23.y, inv, up));
    ((float4*)out)[i] = o;
}

// ---------------- K5: fixup the <=50 scattered-p entries per row --------------
__global__ void __launch_bounds__(64) k_fix(const int* __restrict__ idx,
                                            float* __restrict__ out)
{
    int row = blockIdx.x, tid = threadIdx.x;
    if (tid < NH) {
        float pv = g_pval[row * NH + tid];
        if (pv >= 0.f) {
            int e = idx[row * NH + tid];
            float es = __half2float(g_es[(size_t)row * NE + e]);
            out[(size_t)row * NE + e] = __logf(0.5f * pv + 0.5f * es * g_inv[row]);
        }
    }
}

// ---------------- launch ------------------------------------------------------
extern "C" void kernel_launch(void* const* d_in, const int* in_sizes, int n_in,
                              void* d_out, int out_size)
{
    const int*   idx   = (const int*)d_in[0];
    const int*   times = (const int*)d_in[1];
    const float* emb   = (const float*)d_in[2];
    const float* Wsw   = (const float*)d_in[3];
    const float* Wsb   = (const float*)d_in[4];
    const float* mlpw  = (const float*)d_in[5];
    const float* mlpb  = (const float*)d_in[6];
    float*       out   = (float*)d_out;

    cudaFuncSetAttribute(k_x,     cudaFuncAttributeMaxDynamicSharedMemorySize, 51456);
    cudaFuncSetAttribute(k_rout2, cudaFuncAttributeMaxDynamicSharedMemorySize, 42496);
    cudaFuncSetAttribute(k_gemm,  cudaFuncAttributeMaxDynamicSharedMemorySize, 112640);

    k_convw  <<<NE, 256>>>(mlpw);
    k_x      <<<BATCH * NH / 32, 256, 51456>>>(idx, emb, Wsw, Wsb);
    k_rout2  <<<BATCH, 256, 42496>>>(times);
    k_pprep  <<<BATCH, 64>>>(idx);
    k_gemm   <<<dim3(GX, BATCH / 128), 256, 112640>>>(mlpb);
    k_rowsum <<<BATCH, 128>>>();
    k_final  <<<(BATCH * NE / 4) / 256, 256>>>(out);   // 25000 blocks, exact cover
    k_fix    <<<BATCH, 64>>>(idx, out);
}